// round 15
// baseline (speedup 1.0000x reference)
#include <cuda_runtime.h>
#include <cuda_fp16.h>
#include <cstdint>

// Problem constants
#define T_TOK 2048
#define HDIM  1024
#define FDIM  1024
#define NEXP  8
#define TOPK  2
#define NPAIR (T_TOK * TOPK)

// Tiling (R6/R11 config)
#define BM 128
#define BK 32
#define NCH (HDIM / BK)          // 32 chunks
#define MAX_TILES 40
#define PAD_ROWS (MAX_TILES * BM)

// fp16 smem rows, stride 80 B (5 x 16B granules, gcd(5,8)=1 -> ldmatrix
// conflict-free). A: 4-stage cp.async. B: 2-stage reg-pipelined cvt.
#define ROWB 80
#define TILEB (BM * ROWB)        // 10240 B
#define A_STAGES 4
#define SMEM_BYTES (A_STAGES * TILEB + 2 * TILEB)   // 61440

// Scratch (no allocations allowed)
__device__ int    d_sorted[PAD_ROWS];
__device__ int    d_tile_expert[MAX_TILES];
__device__ int    d_ntiles;
__device__ __half d_hs16[(size_t)T_TOK * HDIM];     // 4 MB
__device__ __half d_act[(size_t)PAD_ROWS * FDIM];   // 10 MB

// ---------------------------------------------------------------------------
// Helpers
// ---------------------------------------------------------------------------
__device__ __forceinline__ uint32_t smem_u32(const void* p) {
    uint32_t a;
    asm("{ .reg .u64 t; cvta.to.shared.u64 t, %1; cvt.u32.u64 %0, t; }" : "=r"(a) : "l"(p));
    return a;
}
__device__ __forceinline__ uint32_t f2h2(float lo, float hi) {
    __half2 h = __floats2half2_rn(lo, hi);
    return *(uint32_t*)&h;
}
__device__ __forceinline__ void cpa16(uint32_t dst, const void* src) {
    asm volatile("cp.async.cg.shared.global [%0], [%1], 16;" :: "r"(dst), "l"(src));
}
#define CPA_COMMIT() asm volatile("cp.async.commit_group;" ::: "memory")
#define CPA_WAIT2()  asm volatile("cp.async.wait_group 2;" ::: "memory")

__device__ __forceinline__ void ldsm4(uint32_t* r, uint32_t addr) {
    asm volatile("ldmatrix.sync.aligned.m8n8.x4.shared.b16 {%0,%1,%2,%3}, [%4];"
                 : "=r"(r[0]), "=r"(r[1]), "=r"(r[2]), "=r"(r[3]) : "r"(addr));
}
__device__ __forceinline__ void mma16(float* d, const uint32_t* a, const uint32_t* b) {
    asm volatile(
        "mma.sync.aligned.m16n8k16.row.col.f32.f16.f16.f32 "
        "{%0,%1,%2,%3}, {%4,%5,%6,%7}, {%8,%9}, {%0,%1,%2,%3};"
        : "+f"(d[0]), "+f"(d[1]), "+f"(d[2]), "+f"(d[3])
        : "r"(a[0]), "r"(a[1]), "r"(a[2]), "r"(a[3]), "r"(b[0]), "r"(b[1]));
}
// PDL intrinsics
__device__ __forceinline__ void pdl_trigger() {
    asm volatile("griddepcontrol.launch_dependents;" ::: "memory");
}
__device__ __forceinline__ void pdl_wait() {
    asm volatile("griddepcontrol.wait;" ::: "memory");
}

// ---------------------------------------------------------------------------
// Setup: block 0 = routing (warp-aggregated atomics); blocks 1..512 =
// hs conv + out zero. pdl_trigger at END of each block.
// ---------------------------------------------------------------------------
__global__ void setup_kernel(const float* __restrict__ hs, const int* __restrict__ ids,
                             float* __restrict__ out) {
    int tid = threadIdx.x;
    if (blockIdx.x == 0) {
        __shared__ int s_cnt[NEXP], s_start[NEXP], s_cur[NEXP];
        int lane = tid & 31;
        if (tid < NEXP) s_cnt[tid] = 0;
        __syncthreads();
        // Count phase: warp-aggregated (leader atomic per warp x expert)
        for (int p = tid; p < NPAIR; p += blockDim.x) {
            int e = ids[p];
            unsigned mask = __match_any_sync(0xFFFFFFFFu, e);
            int leader = __ffs(mask) - 1;
            if (lane == leader) atomicAdd(&s_cnt[e], __popc(mask));
        }
        __syncthreads();
        if (tid == 0) {
            int acc = 0, nt = 0;
            for (int e = 0; e < NEXP; e++) {
                s_start[e] = acc;
                int te = (s_cnt[e] + BM - 1) / BM;
                for (int i = 0; i < te; i++) d_tile_expert[nt + i] = e;
                nt += te;
                acc += te * BM;
            }
            d_ntiles = nt;
        }
        __syncthreads();
        for (int i = tid; i < PAD_ROWS; i += blockDim.x) d_sorted[i] = -1;
        if (tid < NEXP) s_cur[tid] = s_start[tid];
        __syncthreads();
        // Scatter phase: warp-aggregated base + intra-warp rank
        for (int p = tid; p < NPAIR; p += blockDim.x) {
            int e = ids[p];
            unsigned mask = __match_any_sync(0xFFFFFFFFu, e);
            int leader = __ffs(mask) - 1;
            int base = 0;
            if (lane == leader) base = atomicAdd(&s_cur[e], __popc(mask));
            base = __shfl_sync(mask, base, leader);
            int rank = __popc(mask & ((1u << lane) - 1u));
            d_sorted[base + rank] = p;
        }
        __syncthreads();
    } else {
        // hs conv: 262144 uint4; 512 blocks x 256 thr x 2
        int j = (blockIdx.x - 1) * 512 + tid;
        const float4* s = (const float4*)hs;
        #pragma unroll
        for (int it = 0; it < 2; it++) {
            int i = j + it * 256;
            float4 a = s[i * 2], b = s[i * 2 + 1];
            uint4 o;
            o.x = f2h2(a.x, a.y); o.y = f2h2(a.z, a.w);
            o.z = f2h2(b.x, b.y); o.w = f2h2(b.z, b.w);
            ((uint4*)d_hs16)[i] = o;
        }
        // d_out zero: 524288 uint4; 512 blocks x 256 thr x 4
        uint4 z = make_uint4(0, 0, 0, 0);
        int base = (blockIdx.x - 1) * 1024 + tid;
        #pragma unroll
        for (int it = 0; it < 4; it++)
            ((uint4*)out)[base + it * 256] = z;
    }
    pdl_trigger();   // all of this block's work done
}

// ---------------------------------------------------------------------------
// GEMM1 (R11 body): act = silu(x@Wg^T)*(x@Wu^T). Grid (40,16), 2 CTA/SM.
// Trigger at TOP; wait immediately (setup triggered at end -> fence).
// ---------------------------------------------------------------------------
__global__ __launch_bounds__(128, 2)
void gemm1_kernel(const float* __restrict__ gw) {
    pdl_trigger();
    pdl_wait();      // setup grid complete; its writes visible

    int tile = blockIdx.x;
    if (tile >= d_ntiles) return;
    int e  = d_tile_expert[tile];
    int f0 = blockIdx.y * 64;

    extern __shared__ __align__(16) char smem[];
    __shared__ int s_tok[BM];

    int tid = threadIdx.x, lane = tid & 31, warp = tid >> 5;
    if (tid < BM) {
        int sp = d_sorted[tile * BM + tid];
        s_tok[tid] = (sp >= 0) ? (sp >> 1) : 0;
    }
    __syncthreads();

    const float* gwe = gw + (size_t)e * (2 * FDIM) * HDIM;
    uint32_t sb = smem_u32(smem);
    uint32_t bbase0 = sb + A_STAGES * TILEB;

    int ar[4], ac8[4];
    const __half* asrc[4];
    #pragma unroll
    for (int i = 0; i < 4; i++) {
        int idx = tid + i * 128;
        ar[i] = idx >> 2; ac8[i] = idx & 3;
        asrc[i] = d_hs16 + (size_t)s_tok[ar[i]] * HDIM + ac8[i] * 8;
    }
    auto issueA = [&](int c) {
        uint32_t ab = sb + (c & 3) * TILEB;
        #pragma unroll
        for (int i = 0; i < 4; i++)
            cpa16(ab + ar[i] * ROWB + ac8[i] * 16, asrc[i] + c * BK);
    };

    int br[8], bc4[8];
    const float* bsrc[8];
    #pragma unroll
    for (int i = 0; i < 8; i++) {
        int idx = tid + i * 128;
        br[i] = idx >> 3; bc4[i] = idx & 7;
        int grow = (br[i] < 64) ? (f0 + br[i]) : (FDIM + f0 + (br[i] - 64));
        bsrc[i] = gwe + (size_t)grow * HDIM + bc4[i] * 4;
    }
    float4 bbuf[8];
    auto loadB = [&](int c) {
        #pragma unroll
        for (int i = 0; i < 8; i++) bbuf[i] = *(const float4*)(bsrc[i] + c * BK);
    };
    auto stsB = [&](int c) {
        char* bs = smem + A_STAGES * TILEB + (c & 1) * TILEB;
        #pragma unroll
        for (int i = 0; i < 8; i++)
            *(uint2*)(bs + br[i] * ROWB + bc4[i] * 8) =
                make_uint2(f2h2(bbuf[i].x, bbuf[i].y), f2h2(bbuf[i].z, bbuf[i].w));
    };

    int wm = warp & 1, wn = warp >> 1;
    int m_base = wm * 64, f_base = wn * 32;

    int g = lane >> 3;
    int a_row = (g & 1) * 8 + (lane & 7);
    int a_kb  = (g >> 1) * 16;
    int b_row = (g >> 1) * 8 + (lane & 7);
    int b_kb  = (g & 1) * 16;

    float accG[4][4][4], accU[4][4][4];
    #pragma unroll
    for (int mt = 0; mt < 4; mt++)
        #pragma unroll
        for (int nt = 0; nt < 4; nt++)
            #pragma unroll
            for (int i = 0; i < 4; i++) { accG[mt][nt][i] = 0.f; accU[mt][nt][i] = 0.f; }

    issueA(0); CPA_COMMIT();
    issueA(1); CPA_COMMIT();
    issueA(2); CPA_COMMIT();
    loadB(0); stsB(0); loadB(1);

    for (int c = 0; c < NCH; c++) {
        CPA_WAIT2();
        __syncthreads();

        uint32_t Ab = sb + (c & 3) * TILEB;
        uint32_t Bb = bbase0 + (c & 1) * TILEB;

        #pragma unroll
        for (int kf = 0; kf < 2; kf++) {
            uint32_t af[4][4], bg[8], bu[8];
            #pragma unroll
            for (int mt = 0; mt < 4; mt++)
                ldsm4(af[mt], Ab + (m_base + mt * 16 + a_row) * ROWB + kf * 32 + a_kb);
            #pragma unroll
            for (int p = 0; p < 2; p++) {
                ldsm4(bg + p * 4, Bb + (f_base + p * 16 + b_row) * ROWB + kf * 32 + b_kb);
                ldsm4(bu + p * 4, Bb + (64 + f_base + p * 16 + b_row) * ROWB + kf * 32 + b_kb);
            }
            #pragma unroll
            for (int mt = 0; mt < 4; mt++)
                #pragma unroll
                for (int nt = 0; nt < 4; nt++) {
                    mma16(accG[mt][nt], af[mt], bg + nt * 2);
                    mma16(accU[mt][nt], af[mt], bu + nt * 2);
                }
        }
        if (c + 1 < NCH) stsB(c + 1);
        if (c + 2 < NCH) loadB(c + 2);
        if (c + 3 < NCH) issueA(c + 3);
        CPA_COMMIT();
    }

    #pragma unroll
    for (int mt = 0; mt < 4; mt++)
        #pragma unroll
        for (int nt = 0; nt < 4; nt++)
            #pragma unroll
            for (int half = 0; half < 2; half++) {
                int r  = m_base + mt * 16 + (lane >> 2) + half * 8;
                int cc = f0 + f_base + nt * 8 + (lane & 3) * 2;
                float g0 = accG[mt][nt][half * 2 + 0];
                float g1 = accG[mt][nt][half * 2 + 1];
                float u0 = accU[mt][nt][half * 2 + 0];
                float u1 = accU[mt][nt][half * 2 + 1];
                float a0 = g0 / (1.f + __expf(-g0)) * u0;
                float a1 = g1 / (1.f + __expf(-g1)) * u1;
                *(__half2*)&d_act[(size_t)(tile * BM + r) * FDIM + cc] =
                    __floats2half2_rn(a0, a1);
            }
}

// ---------------------------------------------------------------------------
// GEMM2 (R11 body): out[t] += tw[pair] * (act @ Wd[e]^T). Grid (40,8).
// Launches during gemm1's last wave; B prefetch pre-wait; pdl_wait before
// touching d_act. Atomic epilogue (2 commutative fp32 adds).
// ---------------------------------------------------------------------------
__global__ __launch_bounds__(128, 2)
void gemm2_kernel(const float* __restrict__ dw, const float* __restrict__ tw,
                  float* __restrict__ out) {
    pdl_trigger();
    int tile = blockIdx.x;
    if (tile >= d_ntiles) { pdl_wait(); return; }
    int e  = d_tile_expert[tile];
    int h0 = blockIdx.y * 128;

    extern __shared__ __align__(16) char smem[];

    int tid = threadIdx.x, lane = tid & 31, warp = tid >> 5;
    const float* dwe = dw + (size_t)e * HDIM * FDIM;
    uint32_t sb = smem_u32(smem);
    uint32_t bbase0 = sb + A_STAGES * TILEB;

    // B pointers + stage-0/1 prefetch (dw input + setup outputs only)
    int br[8], bc4[8];
    #pragma unroll
    for (int i = 0; i < 8; i++) {
        int idx = tid + i * 128;
        br[i] = idx >> 3; bc4[i] = idx & 7;
    }
    float4 bbuf[8];
    auto loadB = [&](int c) {
        #pragma unroll
        for (int i = 0; i < 8; i++)
            bbuf[i] = *(const float4*)(dwe + (size_t)(h0 + br[i]) * FDIM + c * BK + bc4[i] * 4);
    };
    auto stsB = [&](int c) {
        char* bs = smem + A_STAGES * TILEB + (c & 1) * TILEB;
        #pragma unroll
        for (int i = 0; i < 8; i++)
            *(uint2*)(bs + br[i] * ROWB + bc4[i] * 8) =
                make_uint2(f2h2(bbuf[i].x, bbuf[i].y), f2h2(bbuf[i].z, bbuf[i].w));
    };
    loadB(0); stsB(0); loadB(1);
    __syncthreads();

    pdl_wait();      // gemm1 grid complete: d_act readable

    const __half* arow = d_act + (size_t)tile * BM * FDIM;
    int ar[4], ac8[4];
    #pragma unroll
    for (int i = 0; i < 4; i++) {
        int idx = tid + i * 128;
        ar[i] = idx >> 2; ac8[i] = idx & 3;
    }
    auto issueA = [&](int c) {
        uint32_t ab = sb + (c & 3) * TILEB;
        #pragma unroll
        for (int i = 0; i < 4; i++)
            cpa16(ab + ar[i] * ROWB + ac8[i] * 16,
                  arow + (size_t)ar[i] * FDIM + c * BK + ac8[i] * 8);
    };

    int wm = warp & 1, wn = warp >> 1;
    int m_base = wm * 64, n_base = wn * 64;

    int g = lane >> 3;
    int a_row = (g & 1) * 8 + (lane & 7);
    int a_kb  = (g >> 1) * 16;
    int b_row = (g >> 1) * 8 + (lane & 7);
    int b_kb  = (g & 1) * 16;

    float acc[4][8][4];
    #pragma unroll
    for (int mt = 0; mt < 4; mt++)
        #pragma unroll
        for (int nt = 0; nt < 8; nt++)
            #pragma unroll
            for (int i = 0; i < 4; i++) acc[mt][nt][i] = 0.f;

    issueA(0); CPA_COMMIT();
    issueA(1); CPA_COMMIT();
    issueA(2); CPA_COMMIT();

    for (int c = 0; c < NCH; c++) {
        CPA_WAIT2();
        __syncthreads();

        uint32_t Ab = sb + (c & 3) * TILEB;
        uint32_t Bb = bbase0 + (c & 1) * TILEB;

        #pragma unroll
        for (int kf = 0; kf < 2; kf++) {
            uint32_t af[4][4], bf[16];
            #pragma unroll
            for (int mt = 0; mt < 4; mt++)
                ldsm4(af[mt], Ab + (m_base + mt * 16 + a_row) * ROWB + kf * 32 + a_kb);
            #pragma unroll
            for (int p = 0; p < 4; p++)
                ldsm4(bf + p * 4, Bb + (n_base + p * 16 + b_row) * ROWB + kf * 32 + b_kb);
            #pragma unroll
            for (int mt = 0; mt < 4; mt++)
                #pragma unroll
                for (int nt = 0; nt < 8; nt++)
                    mma16(acc[mt][nt], af[mt], bf + nt * 2);
        }
        if (c + 1 < NCH) stsB(c + 1);
        if (c + 2 < NCH) loadB(c + 2);
        if (c + 3 < NCH) issueA(c + 3);
        CPA_COMMIT();
    }

    // Epilogue: 2 commutative fp32 atomicAdds per output -> deterministic.
    #pragma unroll
    for (int mt = 0; mt < 4; mt++)
        #pragma unroll
        for (int half = 0; half < 2; half++) {
            int r  = m_base + mt * 16 + (lane >> 2) + half * 8;
            int sp = d_sorted[tile * BM + r];
            if (sp < 0) continue;
            float wt = tw[sp];
            float* orow = out + (size_t)(sp >> 1) * HDIM;
            #pragma unroll
            for (int nt = 0; nt < 8; nt++) {
                int cc = h0 + n_base + nt * 8 + (lane & 3) * 2;
                atomicAdd(&orow[cc],     wt * acc[mt][nt][half * 2 + 0]);
                atomicAdd(&orow[cc + 1], wt * acc[mt][nt][half * 2 + 1]);
            }
        }
}

// ---------------------------------------------------------------------------
extern "C" void kernel_launch(void* const* d_in, const int* in_sizes, int n_in,
                              void* d_out, int out_size) {
    const float* hs  = (const float*)d_in[0];
    const float* tw  = (const float*)d_in[1];
    const int*   ids = (const int*)d_in[2];
    const float* gw  = (const float*)d_in[3];
    const float* dw  = (const float*)d_in[4];
    float* out = (float*)d_out;

    cudaFuncSetAttribute(gemm1_kernel, cudaFuncAttributeMaxDynamicSharedMemorySize, SMEM_BYTES);
    cudaFuncSetAttribute(gemm2_kernel, cudaFuncAttributeMaxDynamicSharedMemorySize, SMEM_BYTES);

    cudaLaunchAttribute attr[1];
    attr[0].id = cudaLaunchAttributeProgrammaticStreamSerialization;
    attr[0].val.programmaticStreamSerializationAllowed = 1;

    setup_kernel<<<513, 256>>>(hs, ids, out);

    {   // gemm1: PDL secondary of setup (setup triggers at END -> race-free)
        cudaLaunchConfig_t cfg = {};
        cfg.gridDim = dim3(MAX_TILES, FDIM / 64, 1); cfg.blockDim = dim3(128, 1, 1);
        cfg.dynamicSmemBytes = SMEM_BYTES;
        cfg.attrs = attr; cfg.numAttrs = 1;
        cudaLaunchKernelEx(&cfg, gemm1_kernel, gw);
    }
    {   // gemm2: PDL secondary of gemm1 (launches during gemm1's last wave)
        cudaLaunchConfig_t cfg = {};
        cfg.gridDim = dim3(MAX_TILES, HDIM / 128, 1); cfg.blockDim = dim3(128, 1, 1);
        cfg.dynamicSmemBytes = SMEM_BYTES;
        cfg.attrs = attr; cfg.numAttrs = 1;
        cudaLaunchKernelEx(&cfg, gemm2_kernel, dw, tw, out);
    }
}

// round 16
// speedup vs baseline: 1.0669x; 1.0669x over previous
#include <cuda_runtime.h>
#include <cuda_fp16.h>
#include <cstdint>

// Problem constants
#define T_TOK 2048
#define HDIM  1024
#define FDIM  1024
#define NEXP  8
#define TOPK  2
#define NPAIR (T_TOK * TOPK)

// Tiling (R6/R11 config)
#define BM 128
#define BK 32
#define NCH (HDIM / BK)          // 32 chunks
#define MAX_TILES 40
#define PAD_ROWS (MAX_TILES * BM)

// fp16 smem rows, stride 80 B (5 x 16B granules, gcd(5,8)=1 -> ldmatrix
// conflict-free). A: 4-stage cp.async. B: 2-stage reg-pipelined cvt.
#define ROWB 80
#define TILEB (BM * ROWB)        // 10240 B
#define A_STAGES 4
#define SMEM_BYTES (A_STAGES * TILEB + 2 * TILEB)   // 61440

// Scratch (no allocations allowed)
__device__ int    d_sorted[PAD_ROWS];
__device__ int    d_tile_expert[MAX_TILES];
__device__ int    d_ntiles;
__device__ __half d_hs16[(size_t)T_TOK * HDIM];     // 4 MB
__device__ __half d_act[(size_t)PAD_ROWS * FDIM];   // 10 MB

// ---------------------------------------------------------------------------
// Helpers
// ---------------------------------------------------------------------------
__device__ __forceinline__ uint32_t smem_u32(const void* p) {
    uint32_t a;
    asm("{ .reg .u64 t; cvta.to.shared.u64 t, %1; cvt.u32.u64 %0, t; }" : "=r"(a) : "l"(p));
    return a;
}
__device__ __forceinline__ uint32_t f2h2(float lo, float hi) {
    __half2 h = __floats2half2_rn(lo, hi);
    return *(uint32_t*)&h;
}
__device__ __forceinline__ void cpa16(uint32_t dst, const void* src) {
    asm volatile("cp.async.cg.shared.global [%0], [%1], 16;" :: "r"(dst), "l"(src));
}
#define CPA_COMMIT() asm volatile("cp.async.commit_group;" ::: "memory")
#define CPA_WAIT2()  asm volatile("cp.async.wait_group 2;" ::: "memory")

__device__ __forceinline__ void ldsm4(uint32_t* r, uint32_t addr) {
    asm volatile("ldmatrix.sync.aligned.m8n8.x4.shared.b16 {%0,%1,%2,%3}, [%4];"
                 : "=r"(r[0]), "=r"(r[1]), "=r"(r[2]), "=r"(r[3]) : "r"(addr));
}
__device__ __forceinline__ void mma16(float* d, const uint32_t* a, const uint32_t* b) {
    asm volatile(
        "mma.sync.aligned.m16n8k16.row.col.f32.f16.f16.f32 "
        "{%0,%1,%2,%3}, {%4,%5,%6,%7}, {%8,%9}, {%0,%1,%2,%3};"
        : "+f"(d[0]), "+f"(d[1]), "+f"(d[2]), "+f"(d[3])
        : "r"(a[0]), "r"(a[1]), "r"(a[2]), "r"(a[3]), "r"(b[0]), "r"(b[1]));
}
// PDL intrinsics
__device__ __forceinline__ void pdl_trigger() {
    asm volatile("griddepcontrol.launch_dependents;" ::: "memory");
}
__device__ __forceinline__ void pdl_wait() {
    asm volatile("griddepcontrol.wait;" ::: "memory");
}

// ---------------------------------------------------------------------------
// Setup: block 0 = routing with 64 sub-counters (8 experts x 8 warps ->
// ~8x less atomic contention); blocks 1..512 = hs conv + out zero.
// pdl_trigger at END of each block.
// ---------------------------------------------------------------------------
__global__ void setup_kernel(const float* __restrict__ hs, const int* __restrict__ ids,
                             float* __restrict__ out) {
    int tid = threadIdx.x;
    if (blockIdx.x == 0) {
        __shared__ int s_cnt[NEXP * 8], s_sub[NEXP * 8];
        int w = tid >> 5;                 // warp id 0..7
        if (tid < NEXP * 8) s_cnt[tid] = 0;
        __syncthreads();
        // Count into per-(expert, warp) sub-counters
        for (int p = tid; p < NPAIR; p += blockDim.x)
            atomicAdd(&s_cnt[ids[p] * 8 + w], 1);
        __syncthreads();
        if (tid == 0) {
            int acc = 0, nt = 0;
            for (int e = 0; e < NEXP; e++) {
                // expert total
                int ce = 0;
                #pragma unroll
                for (int k = 0; k < 8; k++) ce += s_cnt[e * 8 + k];
                // BM-aligned segment + tile table
                int te = (ce + BM - 1) / BM;
                for (int i = 0; i < te; i++) d_tile_expert[nt + i] = e;
                nt += te;
                // sub-segment starts within this expert's segment
                int run = acc;
                #pragma unroll
                for (int k = 0; k < 8; k++) { s_sub[e * 8 + k] = run; run += s_cnt[e * 8 + k]; }
                acc += te * BM;
            }
            d_ntiles = nt;
        }
        __syncthreads();
        for (int i = tid; i < PAD_ROWS; i += blockDim.x) d_sorted[i] = -1;
        __syncthreads();
        // Scatter via per-(expert, warp) cursors (s_sub doubles as cursor)
        for (int p = tid; p < NPAIR; p += blockDim.x) {
            int pos = atomicAdd(&s_sub[ids[p] * 8 + w], 1);
            d_sorted[pos] = p;
        }
        __syncthreads();
    } else {
        // hs conv: 262144 uint4; 512 blocks x 256 thr x 2
        int j = (blockIdx.x - 1) * 512 + tid;
        const float4* s = (const float4*)hs;
        #pragma unroll
        for (int it = 0; it < 2; it++) {
            int i = j + it * 256;
            float4 a = s[i * 2], b = s[i * 2 + 1];
            uint4 o;
            o.x = f2h2(a.x, a.y); o.y = f2h2(a.z, a.w);
            o.z = f2h2(b.x, b.y); o.w = f2h2(b.z, b.w);
            ((uint4*)d_hs16)[i] = o;
        }
        // d_out zero: 524288 uint4; 512 blocks x 256 thr x 4
        uint4 z = make_uint4(0, 0, 0, 0);
        int base = (blockIdx.x - 1) * 1024 + tid;
        #pragma unroll
        for (int it = 0; it < 4; it++)
            ((uint4*)out)[base + it * 256] = z;
    }
    pdl_trigger();   // all of this block's work done
}

// ---------------------------------------------------------------------------
// GEMM1 (R11 body): act = silu(x@Wg^T)*(x@Wu^T). Grid (40,16), 2 CTA/SM.
// Trigger at TOP; wait immediately (setup triggered at end -> fence).
// ---------------------------------------------------------------------------
__global__ __launch_bounds__(128, 2)
void gemm1_kernel(const float* __restrict__ gw) {
    pdl_trigger();
    pdl_wait();      // setup grid complete; its writes visible

    int tile = blockIdx.x;
    if (tile >= d_ntiles) return;
    int e  = d_tile_expert[tile];
    int f0 = blockIdx.y * 64;

    extern __shared__ __align__(16) char smem[];
    __shared__ int s_tok[BM];

    int tid = threadIdx.x, lane = tid & 31, warp = tid >> 5;
    if (tid < BM) {
        int sp = d_sorted[tile * BM + tid];
        s_tok[tid] = (sp >= 0) ? (sp >> 1) : 0;
    }
    __syncthreads();

    const float* gwe = gw + (size_t)e * (2 * FDIM) * HDIM;
    uint32_t sb = smem_u32(smem);
    uint32_t bbase0 = sb + A_STAGES * TILEB;

    int ar[4], ac8[4];
    const __half* asrc[4];
    #pragma unroll
    for (int i = 0; i < 4; i++) {
        int idx = tid + i * 128;
        ar[i] = idx >> 2; ac8[i] = idx & 3;
        asrc[i] = d_hs16 + (size_t)s_tok[ar[i]] * HDIM + ac8[i] * 8;
    }
    auto issueA = [&](int c) {
        uint32_t ab = sb + (c & 3) * TILEB;
        #pragma unroll
        for (int i = 0; i < 4; i++)
            cpa16(ab + ar[i] * ROWB + ac8[i] * 16, asrc[i] + c * BK);
    };

    int br[8], bc4[8];
    const float* bsrc[8];
    #pragma unroll
    for (int i = 0; i < 8; i++) {
        int idx = tid + i * 128;
        br[i] = idx >> 3; bc4[i] = idx & 7;
        int grow = (br[i] < 64) ? (f0 + br[i]) : (FDIM + f0 + (br[i] - 64));
        bsrc[i] = gwe + (size_t)grow * HDIM + bc4[i] * 4;
    }
    float4 bbuf[8];
    auto loadB = [&](int c) {
        #pragma unroll
        for (int i = 0; i < 8; i++) bbuf[i] = *(const float4*)(bsrc[i] + c * BK);
    };
    auto stsB = [&](int c) {
        char* bs = smem + A_STAGES * TILEB + (c & 1) * TILEB;
        #pragma unroll
        for (int i = 0; i < 8; i++)
            *(uint2*)(bs + br[i] * ROWB + bc4[i] * 8) =
                make_uint2(f2h2(bbuf[i].x, bbuf[i].y), f2h2(bbuf[i].z, bbuf[i].w));
    };

    int wm = warp & 1, wn = warp >> 1;
    int m_base = wm * 64, f_base = wn * 32;

    int g = lane >> 3;
    int a_row = (g & 1) * 8 + (lane & 7);
    int a_kb  = (g >> 1) * 16;
    int b_row = (g >> 1) * 8 + (lane & 7);
    int b_kb  = (g & 1) * 16;

    float accG[4][4][4], accU[4][4][4];
    #pragma unroll
    for (int mt = 0; mt < 4; mt++)
        #pragma unroll
        for (int nt = 0; nt < 4; nt++)
            #pragma unroll
            for (int i = 0; i < 4; i++) { accG[mt][nt][i] = 0.f; accU[mt][nt][i] = 0.f; }

    issueA(0); CPA_COMMIT();
    issueA(1); CPA_COMMIT();
    issueA(2); CPA_COMMIT();
    loadB(0); stsB(0); loadB(1);

    for (int c = 0; c < NCH; c++) {
        CPA_WAIT2();
        __syncthreads();

        uint32_t Ab = sb + (c & 3) * TILEB;
        uint32_t Bb = bbase0 + (c & 1) * TILEB;

        #pragma unroll
        for (int kf = 0; kf < 2; kf++) {
            uint32_t af[4][4], bg[8], bu[8];
            #pragma unroll
            for (int mt = 0; mt < 4; mt++)
                ldsm4(af[mt], Ab + (m_base + mt * 16 + a_row) * ROWB + kf * 32 + a_kb);
            #pragma unroll
            for (int p = 0; p < 2; p++) {
                ldsm4(bg + p * 4, Bb + (f_base + p * 16 + b_row) * ROWB + kf * 32 + b_kb);
                ldsm4(bu + p * 4, Bb + (64 + f_base + p * 16 + b_row) * ROWB + kf * 32 + b_kb);
            }
            #pragma unroll
            for (int mt = 0; mt < 4; mt++)
                #pragma unroll
                for (int nt = 0; nt < 4; nt++) {
                    mma16(accG[mt][nt], af[mt], bg + nt * 2);
                    mma16(accU[mt][nt], af[mt], bu + nt * 2);
                }
        }
        if (c + 1 < NCH) stsB(c + 1);
        if (c + 2 < NCH) loadB(c + 2);
        if (c + 3 < NCH) issueA(c + 3);
        CPA_COMMIT();
    }

    #pragma unroll
    for (int mt = 0; mt < 4; mt++)
        #pragma unroll
        for (int nt = 0; nt < 4; nt++)
            #pragma unroll
            for (int half = 0; half < 2; half++) {
                int r  = m_base + mt * 16 + (lane >> 2) + half * 8;
                int cc = f0 + f_base + nt * 8 + (lane & 3) * 2;
                float g0 = accG[mt][nt][half * 2 + 0];
                float g1 = accG[mt][nt][half * 2 + 1];
                float u0 = accU[mt][nt][half * 2 + 0];
                float u1 = accU[mt][nt][half * 2 + 1];
                float a0 = g0 / (1.f + __expf(-g0)) * u0;
                float a1 = g1 / (1.f + __expf(-g1)) * u1;
                *(__half2*)&d_act[(size_t)(tile * BM + r) * FDIM + cc] =
                    __floats2half2_rn(a0, a1);
            }
}

// ---------------------------------------------------------------------------
// GEMM2 (R11 body): out[t] += tw[pair] * (act @ Wd[e]^T). Grid (40,8).
// Launches during gemm1's last wave; B prefetch pre-wait; pdl_wait before
// touching d_act. Atomic epilogue (2 commutative fp32 adds).
// ---------------------------------------------------------------------------
__global__ __launch_bounds__(128, 2)
void gemm2_kernel(const float* __restrict__ dw, const float* __restrict__ tw,
                  float* __restrict__ out) {
    pdl_trigger();
    int tile = blockIdx.x;
    if (tile >= d_ntiles) { pdl_wait(); return; }
    int e  = d_tile_expert[tile];
    int h0 = blockIdx.y * 128;

    extern __shared__ __align__(16) char smem[];

    int tid = threadIdx.x, lane = tid & 31, warp = tid >> 5;
    const float* dwe = dw + (size_t)e * HDIM * FDIM;
    uint32_t sb = smem_u32(smem);
    uint32_t bbase0 = sb + A_STAGES * TILEB;

    // B pointers + stage-0/1 prefetch (dw input + setup outputs only)
    int br[8], bc4[8];
    #pragma unroll
    for (int i = 0; i < 8; i++) {
        int idx = tid + i * 128;
        br[i] = idx >> 3; bc4[i] = idx & 7;
    }
    float4 bbuf[8];
    auto loadB = [&](int c) {
        #pragma unroll
        for (int i = 0; i < 8; i++)
            bbuf[i] = *(const float4*)(dwe + (size_t)(h0 + br[i]) * FDIM + c * BK + bc4[i] * 4);
    };
    auto stsB = [&](int c) {
        char* bs = smem + A_STAGES * TILEB + (c & 1) * TILEB;
        #pragma unroll
        for (int i = 0; i < 8; i++)
            *(uint2*)(bs + br[i] * ROWB + bc4[i] * 8) =
                make_uint2(f2h2(bbuf[i].x, bbuf[i].y), f2h2(bbuf[i].z, bbuf[i].w));
    };
    loadB(0); stsB(0); loadB(1);
    __syncthreads();

    pdl_wait();      // gemm1 grid complete: d_act readable

    const __half* arow = d_act + (size_t)tile * BM * FDIM;
    int ar[4], ac8[4];
    #pragma unroll
    for (int i = 0; i < 4; i++) {
        int idx = tid + i * 128;
        ar[i] = idx >> 2; ac8[i] = idx & 3;
    }
    auto issueA = [&](int c) {
        uint32_t ab = sb + (c & 3) * TILEB;
        #pragma unroll
        for (int i = 0; i < 4; i++)
            cpa16(ab + ar[i] * ROWB + ac8[i] * 16,
                  arow + (size_t)ar[i] * FDIM + c * BK + ac8[i] * 8);
    };

    int wm = warp & 1, wn = warp >> 1;
    int m_base = wm * 64, n_base = wn * 64;

    int g = lane >> 3;
    int a_row = (g & 1) * 8 + (lane & 7);
    int a_kb  = (g >> 1) * 16;
    int b_row = (g >> 1) * 8 + (lane & 7);
    int b_kb  = (g & 1) * 16;

    float acc[4][8][4];
    #pragma unroll
    for (int mt = 0; mt < 4; mt++)
        #pragma unroll
        for (int nt = 0; nt < 8; nt++)
            #pragma unroll
            for (int i = 0; i < 4; i++) acc[mt][nt][i] = 0.f;

    issueA(0); CPA_COMMIT();
    issueA(1); CPA_COMMIT();
    issueA(2); CPA_COMMIT();

    for (int c = 0; c < NCH; c++) {
        CPA_WAIT2();
        __syncthreads();

        uint32_t Ab = sb + (c & 3) * TILEB;
        uint32_t Bb = bbase0 + (c & 1) * TILEB;

        #pragma unroll
        for (int kf = 0; kf < 2; kf++) {
            uint32_t af[4][4], bf[16];
            #pragma unroll
            for (int mt = 0; mt < 4; mt++)
                ldsm4(af[mt], Ab + (m_base + mt * 16 + a_row) * ROWB + kf * 32 + a_kb);
            #pragma unroll
            for (int p = 0; p < 4; p++)
                ldsm4(bf + p * 4, Bb + (n_base + p * 16 + b_row) * ROWB + kf * 32 + b_kb);
            #pragma unroll
            for (int mt = 0; mt < 4; mt++)
                #pragma unroll
                for (int nt = 0; nt < 8; nt++)
                    mma16(acc[mt][nt], af[mt], bf + nt * 2);
        }
        if (c + 1 < NCH) stsB(c + 1);
        if (c + 2 < NCH) loadB(c + 2);
        if (c + 3 < NCH) issueA(c + 3);
        CPA_COMMIT();
    }

    // Epilogue: 2 commutative fp32 atomicAdds per output -> deterministic.
    #pragma unroll
    for (int mt = 0; mt < 4; mt++)
        #pragma unroll
        for (int half = 0; half < 2; half++) {
            int r  = m_base + mt * 16 + (lane >> 2) + half * 8;
            int sp = d_sorted[tile * BM + r];
            if (sp < 0) continue;
            float wt = tw[sp];
            float* orow = out + (size_t)(sp >> 1) * HDIM;
            #pragma unroll
            for (int nt = 0; nt < 8; nt++) {
                int cc = h0 + n_base + nt * 8 + (lane & 3) * 2;
                atomicAdd(&orow[cc],     wt * acc[mt][nt][half * 2 + 0]);
                atomicAdd(&orow[cc + 1], wt * acc[mt][nt][half * 2 + 1]);
            }
        }
}

// ---------------------------------------------------------------------------
extern "C" void kernel_launch(void* const* d_in, const int* in_sizes, int n_in,
                              void* d_out, int out_size) {
    const float* hs  = (const float*)d_in[0];
    const float* tw  = (const float*)d_in[1];
    const int*   ids = (const int*)d_in[2];
    const float* gw  = (const float*)d_in[3];
    const float* dw  = (const float*)d_in[4];
    float* out = (float*)d_out;

    cudaFuncSetAttribute(gemm1_kernel, cudaFuncAttributeMaxDynamicSharedMemorySize, SMEM_BYTES);
    cudaFuncSetAttribute(gemm2_kernel, cudaFuncAttributeMaxDynamicSharedMemorySize, SMEM_BYTES);

    cudaLaunchAttribute attr[1];
    attr[0].id = cudaLaunchAttributeProgrammaticStreamSerialization;
    attr[0].val.programmaticStreamSerializationAllowed = 1;

    setup_kernel<<<513, 256>>>(hs, ids, out);

    {   // gemm1: PDL secondary of setup (setup triggers at END -> race-free)
        cudaLaunchConfig_t cfg = {};
        cfg.gridDim = dim3(MAX_TILES, FDIM / 64, 1); cfg.blockDim = dim3(128, 1, 1);
        cfg.dynamicSmemBytes = SMEM_BYTES;
        cfg.attrs = attr; cfg.numAttrs = 1;
        cudaLaunchKernelEx(&cfg, gemm1_kernel, gw);
    }
    {   // gemm2: PDL secondary of gemm1 (launches during gemm1's last wave)
        cudaLaunchConfig_t cfg = {};
        cfg.gridDim = dim3(MAX_TILES, HDIM / 128, 1); cfg.blockDim = dim3(128, 1, 1);
        cfg.dynamicSmemBytes = SMEM_BYTES;
        cfg.attrs = attr; cfg.numAttrs = 1;
        cudaLaunchKernelEx(&cfg, gemm2_kernel, dw, tw, out);
    }
}

// round 17
// speedup vs baseline: 1.0744x; 1.0070x over previous
#include <cuda_runtime.h>
#include <cuda_fp16.h>
#include <cstdint>

// Problem constants
#define T_TOK 2048
#define HDIM  1024
#define FDIM  1024
#define NEXP  8
#define TOPK  2
#define NPAIR (T_TOK * TOPK)

// Tiling (R6/R11 config)
#define BM 128
#define BK 32
#define NCH (HDIM / BK)          // 32 chunks
#define MAX_TILES 40
#define PAD_ROWS (MAX_TILES * BM)

// fp16 smem rows, stride 80 B (5 x 16B granules, gcd(5,8)=1 -> ldmatrix
// conflict-free). A: 4-stage cp.async. B: 2-stage reg-pipelined cvt.
#define ROWB 80
#define TILEB (BM * ROWB)        // 10240 B
#define A_STAGES 4
#define SMEM_BYTES (A_STAGES * TILEB + 2 * TILEB)   // 61440

// Scratch (no allocations allowed)
__device__ int    d_sorted[PAD_ROWS];
__device__ int    d_tile_expert[MAX_TILES];
__device__ int    d_ntiles;
__device__ __half d_hs16[(size_t)T_TOK * HDIM];     // 4 MB
__device__ __half d_act[(size_t)PAD_ROWS * FDIM];   // 10 MB

// ---------------------------------------------------------------------------
// Helpers
// ---------------------------------------------------------------------------
__device__ __forceinline__ uint32_t smem_u32(const void* p) {
    uint32_t a;
    asm("{ .reg .u64 t; cvta.to.shared.u64 t, %1; cvt.u32.u64 %0, t; }" : "=r"(a) : "l"(p));
    return a;
}
__device__ __forceinline__ uint32_t f2h2(float lo, float hi) {
    __half2 h = __floats2half2_rn(lo, hi);
    return *(uint32_t*)&h;
}
__device__ __forceinline__ void cpa16(uint32_t dst, const void* src) {
    asm volatile("cp.async.cg.shared.global [%0], [%1], 16;" :: "r"(dst), "l"(src));
}
#define CPA_COMMIT() asm volatile("cp.async.commit_group;" ::: "memory")
#define CPA_WAIT2()  asm volatile("cp.async.wait_group 2;" ::: "memory")

__device__ __forceinline__ void ldsm4(uint32_t* r, uint32_t addr) {
    asm volatile("ldmatrix.sync.aligned.m8n8.x4.shared.b16 {%0,%1,%2,%3}, [%4];"
                 : "=r"(r[0]), "=r"(r[1]), "=r"(r[2]), "=r"(r[3]) : "r"(addr));
}
__device__ __forceinline__ void mma16(float* d, const uint32_t* a, const uint32_t* b) {
    asm volatile(
        "mma.sync.aligned.m16n8k16.row.col.f32.f16.f16.f32 "
        "{%0,%1,%2,%3}, {%4,%5,%6,%7}, {%8,%9}, {%0,%1,%2,%3};"
        : "+f"(d[0]), "+f"(d[1]), "+f"(d[2]), "+f"(d[3])
        : "r"(a[0]), "r"(a[1]), "r"(a[2]), "r"(a[3]), "r"(b[0]), "r"(b[1]));
}
// PDL intrinsics
__device__ __forceinline__ void pdl_trigger() {
    asm volatile("griddepcontrol.launch_dependents;" ::: "memory");
}
__device__ __forceinline__ void pdl_wait() {
    asm volatile("griddepcontrol.wait;" ::: "memory");
}

// ---------------------------------------------------------------------------
// Setup. Blocks 0..7: routing, one block per expert, atomic-free
// (ballot histogram + deterministic scatter). Blocks 8..1031: hs conv +
// d_out zero. pdl_trigger at END of each block.
// ---------------------------------------------------------------------------
__global__ void setup_kernel(const float* __restrict__ hs, const int* __restrict__ ids,
                             float* __restrict__ out) {
    int tid = threadIdx.x;
    int bx = blockIdx.x;
    if (bx < NEXP) {
        int e = bx;
        __shared__ int s_hist[8][NEXP];     // per-warp histograms (all experts)
        __shared__ int s_tot[NEXP];
        int w = tid >> 5, lane = tid & 31;
        int pbase = w * 512;                 // 8 warps x 512 ids = 4096

        // Pass 1: full histogram of this warp's id range via ballots
        int h0 = 0, h1 = 0, h2 = 0, h3 = 0, h4 = 0, h5 = 0, h6 = 0, h7 = 0;
        #pragma unroll 4
        for (int it = 0; it < 16; it++) {
            int id = ids[pbase + it * 32 + lane];
            h0 += __popc(__ballot_sync(0xFFFFFFFFu, id == 0));
            h1 += __popc(__ballot_sync(0xFFFFFFFFu, id == 1));
            h2 += __popc(__ballot_sync(0xFFFFFFFFu, id == 2));
            h3 += __popc(__ballot_sync(0xFFFFFFFFu, id == 3));
            h4 += __popc(__ballot_sync(0xFFFFFFFFu, id == 4));
            h5 += __popc(__ballot_sync(0xFFFFFFFFu, id == 5));
            h6 += __popc(__ballot_sync(0xFFFFFFFFu, id == 6));
            h7 += __popc(__ballot_sync(0xFFFFFFFFu, id == 7));
        }
        if (lane == 0) {
            s_hist[w][0] = h0; s_hist[w][1] = h1; s_hist[w][2] = h2; s_hist[w][3] = h3;
            s_hist[w][4] = h4; s_hist[w][5] = h5; s_hist[w][6] = h6; s_hist[w][7] = h7;
        }
        __syncthreads();
        if (w == 0 && lane < NEXP) {
            int t = 0;
            #pragma unroll
            for (int ww = 0; ww < 8; ww++) t += s_hist[ww][lane];
            s_tot[lane] = t;
        }
        __syncthreads();

        // Segment start (rows) for expert e; this warp's base within it
        int start = 0;
        for (int ee = 0; ee < e; ee++)
            start += ((s_tot[ee] + BM - 1) / BM) * BM;
        int wbase = start;
        for (int ww = 0; ww < w; ww++) wbase += s_hist[ww][e];

        // Pass 2: scatter this warp's matches (ballot rank, deterministic)
        int cum = 0;
        #pragma unroll 4
        for (int it = 0; it < 16; it++) {
            int p = pbase + it * 32 + lane;
            int id = ids[p];
            unsigned mask = __ballot_sync(0xFFFFFFFFu, id == e);
            if (id == e) {
                int r = __popc(mask & ((1u << lane) - 1u));
                d_sorted[wbase + cum + r] = p;
            }
            cum += __popc(mask);
        }

        // Pad + tile table for this expert's segment
        int tot = s_tot[e];
        int te = (tot + BM - 1) / BM;
        for (int i = tot + tid; i < te * BM; i += 256)
            d_sorted[start + i] = -1;
        int tstart = start / BM;
        if (tid < te) d_tile_expert[tstart + tid] = e;
        if (e == 0 && tid == 0) {
            int nt = 0;
            for (int ee = 0; ee < NEXP; ee++) nt += (s_tot[ee] + BM - 1) / BM;
            d_ntiles = nt;
        }
    } else {
        int b = bx - NEXP;
        // hs conv: 262144 uint4; 1024 blocks x 256 thr x 1
        int i = b * 256 + tid;
        const float4* s = (const float4*)hs;
        float4 a = s[i * 2], bb = s[i * 2 + 1];
        uint4 o;
        o.x = f2h2(a.x, a.y);  o.y = f2h2(a.z, a.w);
        o.z = f2h2(bb.x, bb.y); o.w = f2h2(bb.z, bb.w);
        ((uint4*)d_hs16)[i] = o;
        // d_out zero: 524288 uint4; 1024 blocks x 256 thr x 2
        uint4 z = make_uint4(0, 0, 0, 0);
        int base = b * 512 + tid;
        ((uint4*)out)[base] = z;
        ((uint4*)out)[base + 256] = z;
    }
    pdl_trigger();   // all of this block's work done
}

// ---------------------------------------------------------------------------
// GEMM1 (R11 body): act = silu(x@Wg^T)*(x@Wu^T). Grid (40,16), 2 CTA/SM.
// Trigger at TOP; wait immediately (setup triggered at end -> fence).
// ---------------------------------------------------------------------------
__global__ __launch_bounds__(128, 2)
void gemm1_kernel(const float* __restrict__ gw) {
    pdl_trigger();
    pdl_wait();      // setup grid complete; its writes visible

    int tile = blockIdx.x;
    if (tile >= d_ntiles) return;
    int e  = d_tile_expert[tile];
    int f0 = blockIdx.y * 64;

    extern __shared__ __align__(16) char smem[];
    __shared__ int s_tok[BM];

    int tid = threadIdx.x, lane = tid & 31, warp = tid >> 5;
    if (tid < BM) {
        int sp = d_sorted[tile * BM + tid];
        s_tok[tid] = (sp >= 0) ? (sp >> 1) : 0;
    }
    __syncthreads();

    const float* gwe = gw + (size_t)e * (2 * FDIM) * HDIM;
    uint32_t sb = smem_u32(smem);
    uint32_t bbase0 = sb + A_STAGES * TILEB;

    int ar[4], ac8[4];
    const __half* asrc[4];
    #pragma unroll
    for (int i = 0; i < 4; i++) {
        int idx = tid + i * 128;
        ar[i] = idx >> 2; ac8[i] = idx & 3;
        asrc[i] = d_hs16 + (size_t)s_tok[ar[i]] * HDIM + ac8[i] * 8;
    }
    auto issueA = [&](int c) {
        uint32_t ab = sb + (c & 3) * TILEB;
        #pragma unroll
        for (int i = 0; i < 4; i++)
            cpa16(ab + ar[i] * ROWB + ac8[i] * 16, asrc[i] + c * BK);
    };

    int br[8], bc4[8];
    const float* bsrc[8];
    #pragma unroll
    for (int i = 0; i < 8; i++) {
        int idx = tid + i * 128;
        br[i] = idx >> 3; bc4[i] = idx & 7;
        int grow = (br[i] < 64) ? (f0 + br[i]) : (FDIM + f0 + (br[i] - 64));
        bsrc[i] = gwe + (size_t)grow * HDIM + bc4[i] * 4;
    }
    float4 bbuf[8];
    auto loadB = [&](int c) {
        #pragma unroll
        for (int i = 0; i < 8; i++) bbuf[i] = *(const float4*)(bsrc[i] + c * BK);
    };
    auto stsB = [&](int c) {
        char* bs = smem + A_STAGES * TILEB + (c & 1) * TILEB;
        #pragma unroll
        for (int i = 0; i < 8; i++)
            *(uint2*)(bs + br[i] * ROWB + bc4[i] * 8) =
                make_uint2(f2h2(bbuf[i].x, bbuf[i].y), f2h2(bbuf[i].z, bbuf[i].w));
    };

    int wm = warp & 1, wn = warp >> 1;
    int m_base = wm * 64, f_base = wn * 32;

    int g = lane >> 3;
    int a_row = (g & 1) * 8 + (lane & 7);
    int a_kb  = (g >> 1) * 16;
    int b_row = (g >> 1) * 8 + (lane & 7);
    int b_kb  = (g & 1) * 16;

    float accG[4][4][4], accU[4][4][4];
    #pragma unroll
    for (int mt = 0; mt < 4; mt++)
        #pragma unroll
        for (int nt = 0; nt < 4; nt++)
            #pragma unroll
            for (int i = 0; i < 4; i++) { accG[mt][nt][i] = 0.f; accU[mt][nt][i] = 0.f; }

    issueA(0); CPA_COMMIT();
    issueA(1); CPA_COMMIT();
    issueA(2); CPA_COMMIT();
    loadB(0); stsB(0); loadB(1);

    for (int c = 0; c < NCH; c++) {
        CPA_WAIT2();
        __syncthreads();

        uint32_t Ab = sb + (c & 3) * TILEB;
        uint32_t Bb = bbase0 + (c & 1) * TILEB;

        #pragma unroll
        for (int kf = 0; kf < 2; kf++) {
            uint32_t af[4][4], bg[8], bu[8];
            #pragma unroll
            for (int mt = 0; mt < 4; mt++)
                ldsm4(af[mt], Ab + (m_base + mt * 16 + a_row) * ROWB + kf * 32 + a_kb);
            #pragma unroll
            for (int p = 0; p < 2; p++) {
                ldsm4(bg + p * 4, Bb + (f_base + p * 16 + b_row) * ROWB + kf * 32 + b_kb);
                ldsm4(bu + p * 4, Bb + (64 + f_base + p * 16 + b_row) * ROWB + kf * 32 + b_kb);
            }
            #pragma unroll
            for (int mt = 0; mt < 4; mt++)
                #pragma unroll
                for (int nt = 0; nt < 4; nt++) {
                    mma16(accG[mt][nt], af[mt], bg + nt * 2);
                    mma16(accU[mt][nt], af[mt], bu + nt * 2);
                }
        }
        if (c + 1 < NCH) stsB(c + 1);
        if (c + 2 < NCH) loadB(c + 2);
        if (c + 3 < NCH) issueA(c + 3);
        CPA_COMMIT();
    }

    #pragma unroll
    for (int mt = 0; mt < 4; mt++)
        #pragma unroll
        for (int nt = 0; nt < 4; nt++)
            #pragma unroll
            for (int half = 0; half < 2; half++) {
                int r  = m_base + mt * 16 + (lane >> 2) + half * 8;
                int cc = f0 + f_base + nt * 8 + (lane & 3) * 2;
                float g0 = accG[mt][nt][half * 2 + 0];
                float g1 = accG[mt][nt][half * 2 + 1];
                float u0 = accU[mt][nt][half * 2 + 0];
                float u1 = accU[mt][nt][half * 2 + 1];
                float a0 = g0 / (1.f + __expf(-g0)) * u0;
                float a1 = g1 / (1.f + __expf(-g1)) * u1;
                *(__half2*)&d_act[(size_t)(tile * BM + r) * FDIM + cc] =
                    __floats2half2_rn(a0, a1);
            }
}

// ---------------------------------------------------------------------------
// GEMM2 (R11 body): out[t] += tw[pair] * (act @ Wd[e]^T). Grid (40,8).
// Launches during gemm1's last wave; B prefetch pre-wait; pdl_wait before
// touching d_act. Atomic epilogue (2 commutative fp32 adds).
// ---------------------------------------------------------------------------
__global__ __launch_bounds__(128, 2)
void gemm2_kernel(const float* __restrict__ dw, const float* __restrict__ tw,
                  float* __restrict__ out) {
    pdl_trigger();
    int tile = blockIdx.x;
    if (tile >= d_ntiles) { pdl_wait(); return; }
    int e  = d_tile_expert[tile];
    int h0 = blockIdx.y * 128;

    extern __shared__ __align__(16) char smem[];

    int tid = threadIdx.x, lane = tid & 31, warp = tid >> 5;
    const float* dwe = dw + (size_t)e * HDIM * FDIM;
    uint32_t sb = smem_u32(smem);
    uint32_t bbase0 = sb + A_STAGES * TILEB;

    // B pointers + stage-0/1 prefetch (dw input + setup outputs only)
    int br[8], bc4[8];
    #pragma unroll
    for (int i = 0; i < 8; i++) {
        int idx = tid + i * 128;
        br[i] = idx >> 3; bc4[i] = idx & 7;
    }
    float4 bbuf[8];
    auto loadB = [&](int c) {
        #pragma unroll
        for (int i = 0; i < 8; i++)
            bbuf[i] = *(const float4*)(dwe + (size_t)(h0 + br[i]) * FDIM + c * BK + bc4[i] * 4);
    };
    auto stsB = [&](int c) {
        char* bs = smem + A_STAGES * TILEB + (c & 1) * TILEB;
        #pragma unroll
        for (int i = 0; i < 8; i++)
            *(uint2*)(bs + br[i] * ROWB + bc4[i] * 8) =
                make_uint2(f2h2(bbuf[i].x, bbuf[i].y), f2h2(bbuf[i].z, bbuf[i].w));
    };
    loadB(0); stsB(0); loadB(1);
    __syncthreads();

    pdl_wait();      // gemm1 grid complete: d_act readable

    const __half* arow = d_act + (size_t)tile * BM * FDIM;
    int ar[4], ac8[4];
    #pragma unroll
    for (int i = 0; i < 4; i++) {
        int idx = tid + i * 128;
        ar[i] = idx >> 2; ac8[i] = idx & 3;
    }
    auto issueA = [&](int c) {
        uint32_t ab = sb + (c & 3) * TILEB;
        #pragma unroll
        for (int i = 0; i < 4; i++)
            cpa16(ab + ar[i] * ROWB + ac8[i] * 16,
                  arow + (size_t)ar[i] * FDIM + c * BK + ac8[i] * 8);
    };

    int wm = warp & 1, wn = warp >> 1;
    int m_base = wm * 64, n_base = wn * 64;

    int g = lane >> 3;
    int a_row = (g & 1) * 8 + (lane & 7);
    int a_kb  = (g >> 1) * 16;
    int b_row = (g >> 1) * 8 + (lane & 7);
    int b_kb  = (g & 1) * 16;

    float acc[4][8][4];
    #pragma unroll
    for (int mt = 0; mt < 4; mt++)
        #pragma unroll
        for (int nt = 0; nt < 8; nt++)
            #pragma unroll
            for (int i = 0; i < 4; i++) acc[mt][nt][i] = 0.f;

    issueA(0); CPA_COMMIT();
    issueA(1); CPA_COMMIT();
    issueA(2); CPA_COMMIT();

    for (int c = 0; c < NCH; c++) {
        CPA_WAIT2();
        __syncthreads();

        uint32_t Ab = sb + (c & 3) * TILEB;
        uint32_t Bb = bbase0 + (c & 1) * TILEB;

        #pragma unroll
        for (int kf = 0; kf < 2; kf++) {
            uint32_t af[4][4], bf[16];
            #pragma unroll
            for (int mt = 0; mt < 4; mt++)
                ldsm4(af[mt], Ab + (m_base + mt * 16 + a_row) * ROWB + kf * 32 + a_kb);
            #pragma unroll
            for (int p = 0; p < 4; p++)
                ldsm4(bf + p * 4, Bb + (n_base + p * 16 + b_row) * ROWB + kf * 32 + b_kb);
            #pragma unroll
            for (int mt = 0; mt < 4; mt++)
                #pragma unroll
                for (int nt = 0; nt < 8; nt++)
                    mma16(acc[mt][nt], af[mt], bf + nt * 2);
        }
        if (c + 1 < NCH) stsB(c + 1);
        if (c + 2 < NCH) loadB(c + 2);
        if (c + 3 < NCH) issueA(c + 3);
        CPA_COMMIT();
    }

    // Epilogue: 2 commutative fp32 atomicAdds per output -> deterministic.
    #pragma unroll
    for (int mt = 0; mt < 4; mt++)
        #pragma unroll
        for (int half = 0; half < 2; half++) {
            int r  = m_base + mt * 16 + (lane >> 2) + half * 8;
            int sp = d_sorted[tile * BM + r];
            if (sp < 0) continue;
            float wt = tw[sp];
            float* orow = out + (size_t)(sp >> 1) * HDIM;
            #pragma unroll
            for (int nt = 0; nt < 8; nt++) {
                int cc = h0 + n_base + nt * 8 + (lane & 3) * 2;
                atomicAdd(&orow[cc],     wt * acc[mt][nt][half * 2 + 0]);
                atomicAdd(&orow[cc + 1], wt * acc[mt][nt][half * 2 + 1]);
            }
        }
}

// ---------------------------------------------------------------------------
extern "C" void kernel_launch(void* const* d_in, const int* in_sizes, int n_in,
                              void* d_out, int out_size) {
    const float* hs  = (const float*)d_in[0];
    const float* tw  = (const float*)d_in[1];
    const int*   ids = (const int*)d_in[2];
    const float* gw  = (const float*)d_in[3];
    const float* dw  = (const float*)d_in[4];
    float* out = (float*)d_out;

    cudaFuncSetAttribute(gemm1_kernel, cudaFuncAttributeMaxDynamicSharedMemorySize, SMEM_BYTES);
    cudaFuncSetAttribute(gemm2_kernel, cudaFuncAttributeMaxDynamicSharedMemorySize, SMEM_BYTES);

    cudaLaunchAttribute attr[1];
    attr[0].id = cudaLaunchAttributeProgrammaticStreamSerialization;
    attr[0].val.programmaticStreamSerializationAllowed = 1;

    setup_kernel<<<NEXP + 1024, 256>>>(hs, ids, out);

    {   // gemm1: PDL secondary of setup (setup triggers at END -> race-free)
        cudaLaunchConfig_t cfg = {};
        cfg.gridDim = dim3(MAX_TILES, FDIM / 64, 1); cfg.blockDim = dim3(128, 1, 1);
        cfg.dynamicSmemBytes = SMEM_BYTES;
        cfg.attrs = attr; cfg.numAttrs = 1;
        cudaLaunchKernelEx(&cfg, gemm1_kernel, gw);
    }
    {   // gemm2: PDL secondary of gemm1 (launches during gemm1's last wave)
        cudaLaunchConfig_t cfg = {};
        cfg.gridDim = dim3(MAX_TILES, HDIM / 128, 1); cfg.blockDim = dim3(128, 1, 1);
        cfg.dynamicSmemBytes = SMEM_BYTES;
        cfg.attrs = attr; cfg.numAttrs = 1;
        cudaLaunchKernelEx(&cfg, gemm2_kernel, dw, tw, out);
    }
}